// round 8
// baseline (speedup 1.0000x reference)
#include <cuda_runtime.h>

// NSLayer: out = x + (w0*A + ... + w6*A^7 + w7*I) @ x,  A = I - x x^T
// Gram-space: A^k x = x B^k, B = I - x^T x (symmetric).
//   out = x * P,  P = (1+w7) I + sum w_{k-1} B^k     (triangle Horner)
//
// f32x2 pair packing (2 matrices/thread) + smem-staged coalesced I/O.
// R7 fix: inner loops reordered to j-inner with a shared B[i][k] multiplier
// -> operand-reuse cache removes the 3-distinct-bank RF conflict of FFMA2
// (rt 3 -> 2 on the fma pipe).

typedef unsigned long long ull;

#define NMAT (2048 * 128)
#define THREADS 128
#define MATS_PER_CTA 256                 // 2 per thread
#define PAIR_STRIDE 65                   // float2 units; odd -> conflict-free LDS.64
#define SMEM_BYTES (THREADS * PAIR_STRIDE * 8)

__device__ __forceinline__ int tri(int i, int j) {  // i <= j
    return i * 8 - (i * (i + 1)) / 2 + j;
}
__device__ __forceinline__ ull sg2(const ull* T, int i, int j) {
    return (i <= j) ? T[tri(i, j)] : T[tri(j, i)];
}

__device__ __forceinline__ ull pack2(float lo, float hi) {
    ull r; asm("mov.b64 %0,{%1,%2};" : "=l"(r) : "f"(lo), "f"(hi)); return r;
}
__device__ __forceinline__ ull fma2(ull a, ull b, ull c) {
    ull d; asm("fma.rn.f32x2 %0,%1,%2,%3;" : "=l"(d) : "l"(a), "l"(b), "l"(c)); return d;
}
__device__ __forceinline__ ull mul2(ull a, ull b) {
    ull d; asm("mul.rn.f32x2 %0,%1,%2;" : "=l"(d) : "l"(a), "l"(b)); return d;
}
__device__ __forceinline__ ull add2(ull a, ull b) {
    ull d; asm("add.rn.f32x2 %0,%1,%2;" : "=l"(d) : "l"(a), "l"(b)); return d;
}
// volatile scalar weight load: keeps each weight's live range to one step
__device__ __forceinline__ float ldw(const float* p) {
    float v; asm volatile("ld.global.nc.f32 %0,[%1];" : "=f"(v) : "l"(p)); return v;
}

// dst = B * src + wt * I  (symmetric triangles, packed pairs)
// j-inner ordering: B[i][k] is the shared multiplier across the j-loop
// (operand-reuse), 8-wide independent accumulator row (latency hiding).
__device__ __forceinline__ void step2(ull* __restrict__ dst,
                                      const ull* __restrict__ B,
                                      const ull* __restrict__ src, ull wt2) {
#pragma unroll
    for (int i = 0; i < 8; ++i) {
        ull acc[8];
        {
            ull b0 = sg2(B, i, 0);
#pragma unroll
            for (int j = i; j < 8; ++j) acc[j] = mul2(b0, sg2(src, 0, j));
        }
#pragma unroll
        for (int k = 1; k < 8; ++k) {
            ull bk = sg2(B, i, k);
#pragma unroll
            for (int j = i; j < 8; ++j) acc[j] = fma2(bk, sg2(src, k, j), acc[j]);
        }
#pragma unroll
        for (int j = i; j < 8; ++j)
            dst[tri(i, j)] = (i == j) ? add2(acc[j], wt2) : acc[j];
    }
}

__global__ __launch_bounds__(THREADS, 2) void nslayer_kernel(
    const float* __restrict__ x_g,
    const float* __restrict__ w_g,
    float* __restrict__ out_g)
{
    extern __shared__ float sf[];
    const int tid = threadIdx.x;

    // ---- stage x: coalesced global -> interleaved-pair smem ----
    // pair p holds matrices (2p, 2p+1); float offset of (mat m, elem e):
    //   (m>>1)*130 + 2*e + (m&1)
    const float4* gx = reinterpret_cast<const float4*>(x_g)
                     + (size_t)blockIdx.x * (MATS_PER_CTA * 16);
#pragma unroll
    for (int it = 0; it < 32; ++it) {
        int idx = it * THREADS + tid;
        float4 v = gx[idx];
        int gf = idx << 2;
        int m = gf >> 6, e = gf & 63;
        float* s = sf + (m >> 1) * (2 * PAIR_STRIDE) + 2 * e + (m & 1);
        s[0] = v.x; s[2] = v.y; s[4] = v.z; s[6] = v.w;
    }
    __syncthreads();

    ull* my = reinterpret_cast<ull*>(sf) + tid * PAIR_STRIDE;

    // ---- Gram: B = I - x^T x  (packed triangle) ----
    ull B2[36];
    {
#pragma unroll
        for (int k = 0; k < 8; ++k) {
            ull xr[8];
#pragma unroll
            for (int c = 0; c < 8; ++c) xr[c] = my[k * 8 + c];
#pragma unroll
            for (int i = 0; i < 8; ++i) {
                ull xi = xr[i];                     // reused across j
#pragma unroll
                for (int j = i; j < 8; ++j) {
                    if (k == 0) B2[tri(i, j)] = mul2(xi, xr[j]);
                    else        B2[tri(i, j)] = fma2(xi, xr[j], B2[tri(i, j)]);
                }
            }
        }
        const ull m1 = pack2(-1.0f, -1.0f);
        const ull one2 = pack2(1.0f, 1.0f);
#pragma unroll
        for (int i = 0; i < 8; ++i)
#pragma unroll
            for (int j = i; j < 8; ++j)
                B2[tri(i, j)] = fma2(B2[tri(i, j)], m1, (i == j) ? one2 : 0ull);
    }

    // ---- Horner on packed triangles ----
    ull M0[36], M1[36];
    {
        float w6 = ldw(w_g + 6), w5 = ldw(w_g + 5);
        ull w6_2 = pack2(w6, w6), w5_2 = pack2(w5, w5);
#pragma unroll
        for (int i = 0; i < 8; ++i)
#pragma unroll
            for (int j = i; j < 8; ++j) {
                ull v = mul2(B2[tri(i, j)], w6_2);
                M0[tri(i, j)] = (i == j) ? add2(v, w5_2) : v;
            }
    }
    { float w = ldw(w_g + 4); step2(M1, B2, M0, pack2(w, w)); }
    { float w = ldw(w_g + 3); step2(M0, B2, M1, pack2(w, w)); }
    { float w = ldw(w_g + 2); step2(M1, B2, M0, pack2(w, w)); }
    { float w = ldw(w_g + 1); step2(M0, B2, M1, pack2(w, w)); }
    { float w = ldw(w_g + 0); step2(M1, B2, M0, pack2(w, w)); }
    { float w = 1.0f + ldw(w_g + 7); step2(M0, B2, M1, pack2(w, w)); }
    // M0 = P (symmetric, packed)

    // ---- out = x * P  (j-inner, x[i][k] reused), in-place in own slab ----
#pragma unroll
    for (int i = 0; i < 8; ++i) {
        ull xr[8];
#pragma unroll
        for (int c = 0; c < 8; ++c) xr[c] = my[i * 8 + c];
        ull acc[8];
        {
            ull x0 = xr[0];
#pragma unroll
            for (int j = 0; j < 8; ++j) acc[j] = mul2(x0, sg2(M0, 0, j));
        }
#pragma unroll
        for (int k = 1; k < 8; ++k) {
            ull xk = xr[k];
#pragma unroll
            for (int j = 0; j < 8; ++j) acc[j] = fma2(xk, sg2(M0, k, j), acc[j]);
        }
#pragma unroll
        for (int j = 0; j < 8; ++j) my[i * 8 + j] = acc[j];
    }
    __syncthreads();

    // ---- coalesced smem -> global store ----
    float4* go = reinterpret_cast<float4*>(out_g)
               + (size_t)blockIdx.x * (MATS_PER_CTA * 16);
#pragma unroll
    for (int it = 0; it < 32; ++it) {
        int idx = it * THREADS + tid;
        int gf = idx << 2;
        int m = gf >> 6, e = gf & 63;
        const float* s = sf + (m >> 1) * (2 * PAIR_STRIDE) + 2 * e + (m & 1);
        float4 v;
        v.x = s[0]; v.y = s[2]; v.z = s[4]; v.w = s[6];
        go[idx] = v;
    }
}

extern "C" void kernel_launch(void* const* d_in, const int* in_sizes, int n_in,
                              void* d_out, int out_size) {
    const float* x_g = (const float*)d_in[0];   // (2048,128,8,8) fp32
    const float* w_g = (const float*)d_in[1];   // 14 fp32 (w[0..7] used)
    float* out_g = (float*)d_out;

    cudaFuncSetAttribute(nslayer_kernel,
                         cudaFuncAttributeMaxDynamicSharedMemorySize, SMEM_BYTES);

    const int blocks = NMAT / MATS_PER_CTA;     // 1024
    nslayer_kernel<<<blocks, THREADS, SMEM_BYTES>>>(x_g, w_g, out_g);
}